// round 13
// baseline (speedup 1.0000x reference)
#include <cuda_runtime.h>
#include <cuda_bf16.h>

#define NV 32000
#define NB 64
#define NL 1024
#define NH 128

// scratch (no allocs allowed)
__device__ float  g_tab[NV * NH];   // [v][128]: ks in 0..63, ke in 64..127
__device__ float2 g_nrm[NV];        // per-vocab (||ks||^2, ||ke||^2)
__device__ float  g_r[NB * NH];     // [b][128]

// ============================================================================
// K1: vocab table. (byte-identical to the measured 689.6us round)
// ============================================================================
#define XST 68
#define W2ST 132
#define K1_XS   0
#define K1_T1   8704
#define K1_WB   13056
#define K1_RED  21760
#define K1_SMEMF 22272

__global__ void __launch_bounds__(256, 2)
k1_kernel(const float* __restrict__ embed,
          const float* __restrict__ W1, const float* __restrict__ b1,
          const float* __restrict__ W2, const float* __restrict__ b2,
          const float* __restrict__ gamma, const float* __restrict__ beta,
          const float* __restrict__ Wsem, const float* __restrict__ Wepi)
{
    extern __shared__ float sm[];
    float* Xs  = sm + K1_XS;
    float* T1p = sm + K1_T1;
    float* Wb  = sm + K1_WB;
    float* red = sm + K1_RED;

    const int tid = threadIdx.x;
    const int v0  = blockIdx.x * 64;
    const int ty  = tid >> 4, tx = tid & 15;

    for (int idx = tid; idx < 64 * 128; idx += 256) {
        int r = idx >> 7, h = idx & 127;
        Xs[h * XST + r] = __ldg(&embed[(size_t)(v0 + r) * NH + h]);
    }
    __syncthreads();

    float xacc[4][8];
    #pragma unroll
    for (int g = 0; g < 2; g++)
        #pragma unroll
        for (int j = 0; j < 4; j++) {
            int c = g * 64 + 4 * tx + j;
            float bj = __ldg(&b2[c]);
            float4 e = *(const float4*)&Xs[c * XST + 4 * ty];
            xacc[0][g * 4 + j] = e.x + bj;
            xacc[1][g * 4 + j] = e.y + bj;
            xacc[2][g * 4 + j] = e.z + bj;
            xacc[3][g * 4 + j] = e.w + bj;
        }

    for (int p = 0; p < 4; p++) {
        for (int idx = tid; idx < 64 * 128; idx += 256) {
            int k = idx & 127, c = idx >> 7;
            Wb[k * XST + c] = __ldg(&W1[(p * 64 + c) * NH + k]);
        }
        __syncthreads();

        float t1[4][4];
        #pragma unroll
        for (int i = 0; i < 4; i++)
            #pragma unroll
            for (int j = 0; j < 4; j++) t1[i][j] = 0.f;
        #pragma unroll 8
        for (int k = 0; k < 128; k++) {
            float4 av = *(const float4*)&Xs[k * XST + 4 * ty];
            float4 bv = *(const float4*)&Wb[k * XST + 4 * tx];
            float a[4] = {av.x, av.y, av.z, av.w};
            float b[4] = {bv.x, bv.y, bv.z, bv.w};
            #pragma unroll
            for (int i = 0; i < 4; i++)
                #pragma unroll
                for (int j = 0; j < 4; j++) t1[i][j] += a[i] * b[j];
        }
        #pragma unroll
        for (int j = 0; j < 4; j++) {
            int c = 4 * tx + j;
            float bj = __ldg(&b1[p * 64 + c]);
            float4 o;
            o.x = fmaxf(t1[0][j] + bj, 0.f);
            o.y = fmaxf(t1[1][j] + bj, 0.f);
            o.z = fmaxf(t1[2][j] + bj, 0.f);
            o.w = fmaxf(t1[3][j] + bj, 0.f);
            *(float4*)&T1p[c * XST + 4 * ty] = o;
        }
        __syncthreads();

        for (int idx = tid; idx < 64 * 128; idx += 256) {
            int kk = idx & 63, c = idx >> 6;
            Wb[kk * W2ST + c] = __ldg(&W2[c * 256 + p * 64 + kk]);
        }
        __syncthreads();

        #pragma unroll 8
        for (int kk = 0; kk < 64; kk++) {
            float4 av = *(const float4*)&T1p[kk * XST + 4 * ty];
            float4 b0 = *(const float4*)&Wb[kk * W2ST + 4 * tx];
            float4 b1v = *(const float4*)&Wb[kk * W2ST + 64 + 4 * tx];
            float a[4] = {av.x, av.y, av.z, av.w};
            float b[8] = {b0.x, b0.y, b0.z, b0.w, b1v.x, b1v.y, b1v.z, b1v.w};
            #pragma unroll
            for (int i = 0; i < 4; i++)
                #pragma unroll
                for (int j = 0; j < 8; j++) xacc[i][j] += a[i] * b[j];
        }
        __syncthreads();
    }

    #pragma unroll
    for (int g = 0; g < 2; g++)
        #pragma unroll
        for (int j = 0; j < 4; j++) {
            int c = g * 64 + 4 * tx + j;
            float4 o;
            o.x = xacc[0][g * 4 + j];
            o.y = xacc[1][g * 4 + j];
            o.z = xacc[2][g * 4 + j];
            o.w = xacc[3][g * 4 + j];
            *(float4*)&Xs[c * XST + 4 * ty] = o;
        }
    __syncthreads();

    {
        int r = tid & 63, qq = tid >> 6;
        float s1 = 0.f, s2 = 0.f;
        #pragma unroll 8
        for (int hh = 0; hh < 32; hh++) {
            float x = Xs[(qq * 32 + hh) * XST + r];
            s1 += x; s2 += x * x;
        }
        red[qq * 64 + r]       = s1;
        red[256 + qq * 64 + r] = s2;
        __syncthreads();
        float S1 = red[r] + red[64 + r] + red[128 + r] + red[192 + r];
        float S2 = red[256 + r] + red[320 + r] + red[384 + r] + red[448 + r];
        float mu   = S1 * (1.f / 128.f);
        float var  = S2 * (1.f / 128.f) - mu * mu;
        float rstd = rsqrtf(var + 1e-5f);
        #pragma unroll 8
        for (int hh = 0; hh < 32; hh++) {
            int h = qq * 32 + hh;
            float x = Xs[h * XST + r];
            Xs[h * XST + r] = (x - mu) * rstd * __ldg(&gamma[h]) + __ldg(&beta[h]);
        }
    }
    __syncthreads();

    for (int p = 0; p < 2; p++) {
        const float* Wk = p ? Wepi : Wsem;
        for (int idx = tid; idx < 64 * 128; idx += 256) {
            int k = idx & 127, c = idx >> 7;
            Wb[k * XST + c] = __ldg(&Wk[c * NH + k]);
        }
        __syncthreads();
        float acc[4][4];
        #pragma unroll
        for (int i = 0; i < 4; i++)
            #pragma unroll
            for (int j = 0; j < 4; j++) acc[i][j] = 0.f;
        #pragma unroll 8
        for (int k = 0; k < 128; k++) {
            float4 av = *(const float4*)&Xs[k * XST + 4 * ty];
            float4 bv = *(const float4*)&Wb[k * XST + 4 * tx];
            float a[4] = {av.x, av.y, av.z, av.w};
            float b[4] = {bv.x, bv.y, bv.z, bv.w};
            #pragma unroll
            for (int i = 0; i < 4; i++)
                #pragma unroll
                for (int j = 0; j < 4; j++) acc[i][j] += a[i] * b[j];
        }
        #pragma unroll
        for (int i = 0; i < 4; i++) {
            float4 o;
            o.x = acc[i][0]; o.y = acc[i][1]; o.z = acc[i][2]; o.w = acc[i][3];
            *(float4*)&g_tab[(size_t)(v0 + 4 * ty + i) * NH + p * 64 + 4 * tx] = o;
        }
        #pragma unroll
        for (int i = 0; i < 4; i++) {
            float s = acc[i][0] * acc[i][0] + acc[i][1] * acc[i][1]
                    + acc[i][2] * acc[i][2] + acc[i][3] * acc[i][3];
            s += __shfl_xor_sync(0xffffffffu, s, 1);
            s += __shfl_xor_sync(0xffffffffu, s, 2);
            s += __shfl_xor_sync(0xffffffffu, s, 4);
            s += __shfl_xor_sync(0xffffffffu, s, 8);
            if (tx == 0) {
                float* gn = (float*)&g_nrm[v0 + 4 * ty + i];
                gn[p] = s;
            }
        }
        __syncthreads();
    }
}

// ============================================================================
// K2: 512-thread scan. Thread = (part = tid>>8, row = (tid&255)>>2, q = tid&3)
// owning 16 columns of its M row -> m[16], kv[16] per thread (half the
// register state of the 256-thread version) and 4 warps/SMSP for latency
// hiding. Step skeleton identical to the proven R5/R12 shape:
// same-step prefetch+commit, ONE barrier, parity wred, float4 gate read.
// matvec combine: 2 shfl (q bits). err^2 reduce: q==0 lanes (lane%4==0),
// masks {4,8,16} sum 8 rows per warp -> 16 warp partials.
// ============================================================================
__global__ void __launch_bounds__(512, 1)
k2_kernel(const int* __restrict__ seq,
          const float* __restrict__ Wrp, const float* __restrict__ brp)
{
    __shared__ int   seqs[NL];
    __shared__ __align__(16) float slot[2][128];
    __shared__ __align__(16) float wred[2][16];
    __shared__ float cbuf[128];

    const int tid  = threadIdx.x;
    const int b    = blockIdx.x;
    const int part = tid >> 8;          // 0 = s, 1 = e
    const int pt   = tid & 255;
    const int row  = pt >> 2;           // 0..63
    const int q    = tid & 3;           // quarter of the row
    const int lane = tid & 31;
    const int warp = tid >> 5;          // 0..15 (0-7 = s, 8-15 = e)

    for (int idx = tid; idx < NL; idx += 512) seqs[idx] = seq[b * NL + idx];
    __syncthreads();

    // preload k_0 + its norms
    if (tid < 128) slot[0][tid] = __ldg(&g_tab[(size_t)seqs[0] * NH + tid]);
    float2 cn = __ldg(&g_nrm[seqs[0]]);
    float cinv = 1.f / fmaxf(sqrtf(part ? cn.y : cn.x), 1e-12f);
    __syncthreads();

    float m[16];
    #pragma unroll
    for (int c = 0; c < 16; c++) m[c] = 0.f;

    const int kbase = part * 64 + q * 16;

    for (int t = 0; t < NL - 1; t++) {
        const int par = t & 1;
        const int nt  = t + 1;

        // prefetch k_{t+1} and its norms; next inv off critical path
        float pv = 0.f;
        if (tid < 128) pv = __ldg(&g_tab[(size_t)seqs[nt] * NH + tid]);
        float2 pn = __ldg(&g_nrm[seqs[nt]]);
        float pinv = 1.f / fmaxf(sqrtf(part ? pn.y : pn.x), 1e-12f);

        // load my 16 k values
        float kv[16];
        const float* kb = &slot[par][kbase];
        #pragma unroll
        for (int c = 0; c < 4; c++) {
            float4 f = *(const float4*)&kb[4 * c];
            kv[4 * c] = f.x; kv[4 * c + 1] = f.y;
            kv[4 * c + 2] = f.z; kv[4 * c + 3] = f.w;
        }

        // matvec partial over 16 cols (4-way split)
        float p0 = 0.f, p1 = 0.f, p2 = 0.f, p3 = 0.f;
        #pragma unroll
        for (int c = 0; c < 4; c++) {
            p0 += m[4 * c]     * kv[4 * c];
            p1 += m[4 * c + 1] * kv[4 * c + 1];
            p2 += m[4 * c + 2] * kv[4 * c + 2];
            p3 += m[4 * c + 3] * kv[4 * c + 3];
        }
        float pp = (p0 + p1) + (p2 + p3);
        pp += __shfl_xor_sync(0xffffffffu, pp, 1);   // combine 4 quarters
        pp += __shfl_xor_sync(0xffffffffu, pp, 2);

        float kel = slot[par][part * 64 + row];
        float dd  = kel - pp * cinv;

        // err^2 reduce: q==0 lanes (lane%4==0) carry 8 distinct rows per warp
        float v = (q == 0) ? dd * dd : 0.f;
        v += __shfl_xor_sync(0xffffffffu, v, 4);
        v += __shfl_xor_sync(0xffffffffu, v, 8);
        v += __shfl_xor_sync(0xffffffffu, v, 16);
        if (lane == 0) wred[par][warp] = v;

        // commit prefetched k_{t+1} (opposite parity buffer)
        if (tid < 128) slot[nt & 1][tid] = pv;

        __syncthreads();    // the only barrier in the step

        float4 a0 = *(const float4*)&wred[par][0];
        float4 a1 = *(const float4*)&wred[par][4];
        float4 e0 = *(const float4*)&wred[par][8];
        float4 e1 = *(const float4*)&wred[par][12];
        float es2 = ((a0.x + a0.y) + (a0.z + a0.w))
                  + ((a1.x + a1.y) + (a1.z + a1.w));
        float ee2 = ((e0.x + e0.y) + (e0.z + e0.w))
                  + ((e1.x + e1.y) + (e1.z + e1.w));
        bool fire = (es2 >= (0.7f * 0.7f) * cn.x) ||
                    (ee2 >= (0.7f * 0.7f) * cn.y);
        float wf   = part ? ((float)nt * (1.f / (float)NL)) : 1.f;
        float coef = (fire ? 0.05f : 0.f) * wf * cinv * dd;
        #pragma unroll
        for (int c = 0; c < 16; c++) m[c] += coef * kv[c];

        cn = pn; cinv = pinv;
    }

    // final: q-vec = tab row of seq[b][L-1], sits in slot[1]. c = M . q (raw).
    {
        const float* kb = &slot[1][kbase];
        float p0 = 0.f, p1 = 0.f, p2 = 0.f, p3 = 0.f;
        #pragma unroll
        for (int c = 0; c < 4; c++) {
            float4 f = *(const float4*)&kb[4 * c];
            p0 += m[4 * c]     * f.x;
            p1 += m[4 * c + 1] * f.y;
            p2 += m[4 * c + 2] * f.z;
            p3 += m[4 * c + 3] * f.w;
        }
        float pp = (p0 + p1) + (p2 + p3);
        pp += __shfl_xor_sync(0xffffffffu, pp, 1);
        pp += __shfl_xor_sync(0xffffffffu, pp, 2);
        if (q == 0) cbuf[part * 64 + row] = pp;
    }
    __syncthreads();

    // r = Wrp @ c + brp -> g_r   (threads 0..255, 2 per output)
    if (tid < 256) {
        int o = tid >> 1, h2 = tid & 1;
        const float* wr = &Wrp[o * NH + h2 * 64];
        const float* cc = &cbuf[h2 * 64];
        float s = 0.f;
        #pragma unroll 8
        for (int mm = 0; mm < 64; mm++) s += __ldg(&wr[mm]) * cc[mm];
        s += __shfl_xor_sync(0xffffffffu, s, 1);
        if (h2 == 0) g_r[b * NH + o] = s + __ldg(&brp[o]);
    }
}

// ============================================================================
// K3: out[64 x 32000] = r @ Wout^T + bout.  250 CTAs, tile 64b x 128v.
// (byte-identical to the measured 689.6us round)
// ============================================================================
#define K3_RST 65
#define K3_WST 129
#define K3_WS  (128 * K3_RST)
#define K3_SMEMF (K3_WS + 128 * K3_WST)

__global__ void __launch_bounds__(256, 2)
k3_kernel(const float* __restrict__ Wout, const float* __restrict__ bout,
          float* __restrict__ out)
{
    extern __shared__ float sm[];
    float* rs = sm;
    float* Ws = sm + K3_WS;
    const int tid = threadIdx.x;
    const int v0  = blockIdx.x * 128;
    const int ty  = tid >> 4, tx = tid & 15;

    for (int idx = tid; idx < 64 * 128; idx += 256) {
        int bb = idx >> 7, k = idx & 127;
        rs[k * K3_RST + bb] = g_r[idx];
    }
    for (int idx = tid; idx < 128 * 128; idx += 256) {
        int vv = idx >> 7, k = idx & 127;
        Ws[k * K3_WST + vv] = __ldg(&Wout[(size_t)(v0 + vv) * NH + k]);
    }
    __syncthreads();

    float acc0[4][4], acc1[4][4];
    #pragma unroll
    for (int i = 0; i < 4; i++)
        #pragma unroll
        for (int j = 0; j < 4; j++) { acc0[i][j] = 0.f; acc1[i][j] = 0.f; }

    #pragma unroll 4
    for (int k = 0; k < 128; k++) {
        float a[4], b0[4], b1[4];
        #pragma unroll
        for (int i = 0; i < 4; i++) a[i]  = rs[k * K3_RST + 4 * ty + i];
        #pragma unroll
        for (int j = 0; j < 4; j++) b0[j] = Ws[k * K3_WST + 16 * j + tx];
        #pragma unroll
        for (int j = 0; j < 4; j++) b1[j] = Ws[k * K3_WST + 64 + 16 * j + tx];
        #pragma unroll
        for (int i = 0; i < 4; i++)
            #pragma unroll
            for (int j = 0; j < 4; j++) {
                acc0[i][j] += a[i] * b0[j];
                acc1[i][j] += a[i] * b1[j];
            }
    }

    #pragma unroll
    for (int j = 0; j < 4; j++) {
        float bj0 = __ldg(&bout[v0 + 16 * j + tx]);
        float bj1 = __ldg(&bout[v0 + 64 + 16 * j + tx]);
        #pragma unroll
        for (int i = 0; i < 4; i++) {
            size_t base = (size_t)(4 * ty + i) * NV + v0;
            out[base + 16 * j + tx]      = acc0[i][j] + bj0;
            out[base + 64 + 16 * j + tx] = acc1[i][j] + bj1;
        }
    }
}

// ============================================================================
extern "C" void kernel_launch(void* const* d_in, const int* in_sizes, int n_in,
                              void* d_out, int out_size)
{
    const int*   seq   = (const int*)d_in[0];
    const float* embed = (const float*)d_in[1];
    const float* W1    = (const float*)d_in[2];
    const float* b1    = (const float*)d_in[3];
    const float* W2    = (const float*)d_in[4];
    const float* b2    = (const float*)d_in[5];
    const float* gamma = (const float*)d_in[6];
    const float* beta  = (const float*)d_in[7];
    const float* Wsem  = (const float*)d_in[8];
    const float* Wepi  = (const float*)d_in[9];
    const float* Wrp   = (const float*)d_in[10];
    const float* brp   = (const float*)d_in[11];
    const float* Wout  = (const float*)d_in[12];
    const float* bout  = (const float*)d_in[13];
    float* out = (float*)d_out;

    cudaFuncSetAttribute(k1_kernel, cudaFuncAttributeMaxDynamicSharedMemorySize,
                         K1_SMEMF * (int)sizeof(float));
    cudaFuncSetAttribute(k3_kernel, cudaFuncAttributeMaxDynamicSharedMemorySize,
                         K3_SMEMF * (int)sizeof(float));

    k1_kernel<<<NV / 64, 256, K1_SMEMF * sizeof(float)>>>(
        embed, W1, b1, W2, b2, gamma, beta, Wsem, Wepi);
    k2_kernel<<<NB, 512>>>(seq, Wrp, brp);
    k3_kernel<<<NV / 128, 256, K3_SMEMF * sizeof(float)>>>(Wout, bout, out);
}

// round 14
// speedup vs baseline: 1.3081x; 1.3081x over previous
#include <cuda_runtime.h>
#include <cuda_bf16.h>

#define NV 32000
#define NB 64
#define NL 1024
#define NH 128

// scratch (no allocs allowed)
__device__ float  g_tab[NV * NH];   // [v][128]: ks in 0..63, ke in 64..127
__device__ float2 g_nrm[NV];        // per-vocab (||ks||^2, ||ke||^2)
__device__ float  g_r[NB * NH];     // [b][128]

// ============================================================================
// K1: vocab table. 70KB smem -> 3 CTAs/SM (6 warps/SMSP).
// Scratch region (8704 floats) is time-shared:
//   GEMM A: W1 panel [k=128][st68]
//   GEMM B: T1p [c=64][st68] (low half) + W2 half-slice [kk=64][st68] (high),
//           staged twice (cols 0..63, then 64..127)
//   Phase D: Wk panel [k=128][st68]
// All GEMM operand loads are LDS.128 (stride 68 = 16B-aligned rows).
// ============================================================================
#define XST 68
#define K1_XS   0                    // Xs  [128][68] = 8704
#define K1_SCR  8704                 // scratch 8704 floats
#define K1_T1   8704                 // T1p at scratch base   (4352)
#define K1_W2   13056                // W2 half at scratch+4352 (4352)
#define K1_RED  17408                // [512]
#define K1_SMEMF 17920               // floats = 71680 bytes

__global__ void __launch_bounds__(256, 3)
k1_kernel(const float* __restrict__ embed,
          const float* __restrict__ W1, const float* __restrict__ b1,
          const float* __restrict__ W2, const float* __restrict__ b2,
          const float* __restrict__ gamma, const float* __restrict__ beta,
          const float* __restrict__ Wsem, const float* __restrict__ Wepi)
{
    extern __shared__ float sm[];
    float* Xs  = sm + K1_XS;
    float* Wb  = sm + K1_SCR;   // W1 panel / Wk panel
    float* T1p = sm + K1_T1;    // aliases Wb low half (valid after GEMM A)
    float* W2s = sm + K1_W2;    // aliases Wb high half
    float* red = sm + K1_RED;

    const int tid = threadIdx.x;
    const int v0  = blockIdx.x * 64;
    const int ty  = tid >> 4, tx = tid & 15;

    // stage E (transposed, k-major)
    for (int idx = tid; idx < 64 * 128; idx += 256) {
        int r = idx >> 7, h = idx & 127;
        Xs[h * XST + r] = __ldg(&embed[(size_t)(v0 + r) * NH + h]);
    }
    __syncthreads();

    // X accumulators: rows 4ty..4ty+3, cols g*64 + 4tx + j. Init E + b2.
    float xacc[4][8];
    #pragma unroll
    for (int g = 0; g < 2; g++)
        #pragma unroll
        for (int j = 0; j < 4; j++) {
            int c = g * 64 + 4 * tx + j;
            float bj = __ldg(&b2[c]);
            float4 e = *(const float4*)&Xs[c * XST + 4 * ty];
            xacc[0][g * 4 + j] = e.x + bj;
            xacc[1][g * 4 + j] = e.y + bj;
            xacc[2][g * 4 + j] = e.z + bj;
            xacc[3][g * 4 + j] = e.w + bj;
        }

    // ---- FFN: 4 panels of 64 hidden cols ----
    for (int p = 0; p < 4; p++) {
        // stage W1 panel k-major into scratch: Wb[k][c], c = 0..63
        for (int idx = tid; idx < 64 * 128; idx += 256) {
            int k = idx & 127, c = idx >> 7;
            Wb[k * XST + c] = __ldg(&W1[(p * 64 + c) * NH + k]);
        }
        __syncthreads();

        // GEMM A: T1 = relu(E @ W1p^T + b1p), thread tile 4x4 (cols 4tx+j)
        float t1[4][4];
        #pragma unroll
        for (int i = 0; i < 4; i++)
            #pragma unroll
            for (int j = 0; j < 4; j++) t1[i][j] = 0.f;
        #pragma unroll 8
        for (int k = 0; k < 128; k++) {
            float4 av = *(const float4*)&Xs[k * XST + 4 * ty];
            float4 bv = *(const float4*)&Wb[k * XST + 4 * tx];
            float a[4] = {av.x, av.y, av.z, av.w};
            float b[4] = {bv.x, bv.y, bv.z, bv.w};
            #pragma unroll
            for (int i = 0; i < 4; i++)
                #pragma unroll
                for (int j = 0; j < 4; j++) t1[i][j] += a[i] * b[j];
        }
        __syncthreads();    // W1 panel dead; scratch may be overwritten

        // write T1p (scratch low half) + stage W2 half 1 (scratch high half)
        #pragma unroll
        for (int j = 0; j < 4; j++) {
            int c = 4 * tx + j;
            float bj = __ldg(&b1[p * 64 + c]);
            float4 o;
            o.x = fmaxf(t1[0][j] + bj, 0.f);
            o.y = fmaxf(t1[1][j] + bj, 0.f);
            o.z = fmaxf(t1[2][j] + bj, 0.f);
            o.w = fmaxf(t1[3][j] + bj, 0.f);
            *(float4*)&T1p[c * XST + 4 * ty] = o;
        }
        for (int idx = tid; idx < 64 * 64; idx += 256) {
            int kk = idx & 63, c = idx >> 6;   // c = 0..63 (output col half 1)
            W2s[kk * XST + c] = __ldg(&W2[c * 256 + p * 64 + kk]);
        }
        __syncthreads();

        // GEMM B half 1: xacc[.][0..3] += T1p @ W2h1^T
        #pragma unroll 8
        for (int kk = 0; kk < 64; kk++) {
            float4 av = *(const float4*)&T1p[kk * XST + 4 * ty];
            float4 bv = *(const float4*)&W2s[kk * XST + 4 * tx];
            float a[4] = {av.x, av.y, av.z, av.w};
            float b[4] = {bv.x, bv.y, bv.z, bv.w};
            #pragma unroll
            for (int i = 0; i < 4; i++)
                #pragma unroll
                for (int j = 0; j < 4; j++) xacc[i][j] += a[i] * b[j];
        }
        __syncthreads();

        // stage W2 half 2
        for (int idx = tid; idx < 64 * 64; idx += 256) {
            int kk = idx & 63, c = idx >> 6;   // output col 64 + c
            W2s[kk * XST + c] = __ldg(&W2[(64 + c) * 256 + p * 64 + kk]);
        }
        __syncthreads();

        // GEMM B half 2: xacc[.][4..7] += T1p @ W2h2^T
        #pragma unroll 8
        for (int kk = 0; kk < 64; kk++) {
            float4 av = *(const float4*)&T1p[kk * XST + 4 * ty];
            float4 bv = *(const float4*)&W2s[kk * XST + 4 * tx];
            float a[4] = {av.x, av.y, av.z, av.w};
            float b[4] = {bv.x, bv.y, bv.z, bv.w};
            #pragma unroll
            for (int i = 0; i < 4; i++)
                #pragma unroll
                for (int j = 0; j < 4; j++) xacc[i][4 + j] += a[i] * b[j];
        }
        __syncthreads();    // T1p/W2s dead before next panel stages W1
    }

    // write X back into Xs (k-major), float4 over the row dim
    #pragma unroll
    for (int g = 0; g < 2; g++)
        #pragma unroll
        for (int j = 0; j < 4; j++) {
            int c = g * 64 + 4 * tx + j;
            float4 o;
            o.x = xacc[0][g * 4 + j];
            o.y = xacc[1][g * 4 + j];
            o.z = xacc[2][g * 4 + j];
            o.w = xacc[3][g * 4 + j];
            *(float4*)&Xs[c * XST + 4 * ty] = o;
        }
    __syncthreads();

    // ---- LayerNorm in place (population var) ----
    {
        int r = tid & 63, qq = tid >> 6;
        float s1 = 0.f, s2 = 0.f;
        #pragma unroll 8
        for (int hh = 0; hh < 32; hh++) {
            float x = Xs[(qq * 32 + hh) * XST + r];
            s1 += x; s2 += x * x;
        }
        red[qq * 64 + r]       = s1;
        red[256 + qq * 64 + r] = s2;
        __syncthreads();
        float S1 = red[r] + red[64 + r] + red[128 + r] + red[192 + r];
        float S2 = red[256 + r] + red[320 + r] + red[384 + r] + red[448 + r];
        float mu   = S1 * (1.f / 128.f);
        float var  = S2 * (1.f / 128.f) - mu * mu;
        float rstd = rsqrtf(var + 1e-5f);
        #pragma unroll 8
        for (int hh = 0; hh < 32; hh++) {
            int h = qq * 32 + hh;
            float x = Xs[h * XST + r];
            Xs[h * XST + r] = (x - mu) * rstd * __ldg(&gamma[h]) + __ldg(&beta[h]);
        }
    }
    __syncthreads();

    // ---- KK = HLN @ Wk^T -> g_tab, and row norms -> g_nrm ----
    for (int p = 0; p < 2; p++) {
        const float* Wk = p ? Wepi : Wsem;
        for (int idx = tid; idx < 64 * 128; idx += 256) {
            int k = idx & 127, c = idx >> 7;
            Wb[k * XST + c] = __ldg(&Wk[c * NH + k]);
        }
        __syncthreads();
        float acc[4][4];
        #pragma unroll
        for (int i = 0; i < 4; i++)
            #pragma unroll
            for (int j = 0; j < 4; j++) acc[i][j] = 0.f;
        #pragma unroll 8
        for (int k = 0; k < 128; k++) {
            float4 av = *(const float4*)&Xs[k * XST + 4 * ty];
            float4 bv = *(const float4*)&Wb[k * XST + 4 * tx];
            float a[4] = {av.x, av.y, av.z, av.w};
            float b[4] = {bv.x, bv.y, bv.z, bv.w};
            #pragma unroll
            for (int i = 0; i < 4; i++)
                #pragma unroll
                for (int j = 0; j < 4; j++) acc[i][j] += a[i] * b[j];
        }
        #pragma unroll
        for (int i = 0; i < 4; i++) {
            float4 o;
            o.x = acc[i][0]; o.y = acc[i][1]; o.z = acc[i][2]; o.w = acc[i][3];
            *(float4*)&g_tab[(size_t)(v0 + 4 * ty + i) * NH + p * 64 + 4 * tx] = o;
        }
        #pragma unroll
        for (int i = 0; i < 4; i++) {
            float s = acc[i][0] * acc[i][0] + acc[i][1] * acc[i][1]
                    + acc[i][2] * acc[i][2] + acc[i][3] * acc[i][3];
            s += __shfl_xor_sync(0xffffffffu, s, 1);
            s += __shfl_xor_sync(0xffffffffu, s, 2);
            s += __shfl_xor_sync(0xffffffffu, s, 4);
            s += __shfl_xor_sync(0xffffffffu, s, 8);
            if (tx == 0) {
                float* gn = (float*)&g_nrm[v0 + 4 * ty + i];
                gn[p] = s;
            }
        }
        __syncthreads();
    }
}

// ============================================================================
// K2: FROZEN — byte-exact measured-460us scan (R12). 256 threads.
// ============================================================================
__global__ void __launch_bounds__(256, 1)
k2_kernel(const int* __restrict__ seq,
          const float* __restrict__ Wrp, const float* __restrict__ brp)
{
    __shared__ int   seqs[NL];
    __shared__ float slot[2][128];
    __shared__ float wred[2][8];
    __shared__ float cbuf[128];

    const int tid  = threadIdx.x;
    const int b    = blockIdx.x;
    const int part = tid >> 7;          // 0 = s, 1 = e
    const int pt   = tid & 127;
    const int row  = pt >> 1;
    const int h    = pt & 1;
    const int lane = tid & 31;
    const int warp = tid >> 5;

    for (int idx = tid; idx < NL; idx += 256) seqs[idx] = seq[b * NL + idx];
    __syncthreads();

    // preload k_0 + its norms
    {
        int tok = seqs[0];
        if (tid < 128) slot[0][tid] = __ldg(&g_tab[(size_t)tok * NH + tid]);
    }
    float2 cn = __ldg(&g_nrm[seqs[0]]);     // current norms (all threads)
    float  cmy = part ? cn.y : cn.x;
    float  cinv = 1.f / fmaxf(sqrtf(cmy), 1e-12f);
    __syncthreads();

    float m[32];
    #pragma unroll
    for (int c = 0; c < 32; c++) m[c] = 0.f;

    const int kbase = part * 64 + h * 32;

    for (int t = 0; t < NL - 1; t++) {
        const int par = t & 1;
        const int nt  = t + 1;

        // prefetch k_{t+1} and its norms; compute next inv off critical path
        float pv = 0.f;
        if (tid < 128) pv = __ldg(&g_tab[(size_t)seqs[nt] * NH + tid]);
        float2 pn  = __ldg(&g_nrm[seqs[nt]]);
        float  pmy = part ? pn.y : pn.x;
        float  pinv = 1.f / fmaxf(sqrtf(pmy), 1e-12f);

        // load my 32 k values
        float kv[32];
        const float* kb = &slot[par][kbase];
        #pragma unroll
        for (int c = 0; c < 8; c++) {
            float4 f = *(const float4*)&kb[4 * c];
            kv[4 * c] = f.x; kv[4 * c + 1] = f.y;
            kv[4 * c + 2] = f.z; kv[4 * c + 3] = f.w;
        }

        // matvec partial (4-way split accumulation)
        float p0 = 0.f, p1 = 0.f, p2 = 0.f, p3 = 0.f;
        #pragma unroll
        for (int c = 0; c < 8; c++) {
            p0 += m[4 * c]     * kv[4 * c];
            p1 += m[4 * c + 1] * kv[4 * c + 1];
            p2 += m[4 * c + 2] * kv[4 * c + 2];
            p3 += m[4 * c + 3] * kv[4 * c + 3];
        }
        float pp = (p0 + p1) + (p2 + p3);
        pp += __shfl_xor_sync(0xffffffffu, pp, 1);      // combine halves

        float kelem = slot[par][part * 64 + row];
        float dd = kelem - pp * cinv;

        // err^2 reduce: contributing lanes are h==0 (even lanes), 4 levels
        float v = (h == 0) ? dd * dd : 0.f;
        v += __shfl_xor_sync(0xffffffffu, v, 2);
        v += __shfl_xor_sync(0xffffffffu, v, 4);
        v += __shfl_xor_sync(0xffffffffu, v, 8);
        v += __shfl_xor_sync(0xffffffffu, v, 16);
        if (lane == 0) wred[par][warp] = v;

        // commit prefetched k_{t+1} (opposite parity buffer)
        if (tid < 128) slot[nt & 1][tid] = pv;

        __syncthreads();    // the only barrier in the step

        float4 w0 = *(const float4*)&wred[par][0];
        float4 w1 = *(const float4*)&wred[par][4];
        float es2 = (w0.x + w0.y) + (w0.z + w0.w);
        float ee2 = (w1.x + w1.y) + (w1.z + w1.w);
        bool fire = (es2 >= (0.7f * 0.7f) * cn.x) ||
                    (ee2 >= (0.7f * 0.7f) * cn.y);
        float wf   = part ? ((float)nt * (1.f / (float)NL)) : 1.f;
        float coef = (fire ? 0.05f : 0.f) * wf * cinv * dd;
        #pragma unroll
        for (int c = 0; c < 32; c++) m[c] += coef * kv[c];

        // roll prefetched norms into current
        cn = pn; cinv = pinv;
    }

    // final: q = tab row of seq[b][L-1], sits in slot[1]. c = M @ q-part (raw).
    {
        const float* kb = &slot[1][kbase];
        float p0 = 0.f, p1 = 0.f, p2 = 0.f, p3 = 0.f;
        #pragma unroll
        for (int c = 0; c < 8; c++) {
            float4 f = *(const float4*)&kb[4 * c];
            p0 += m[4 * c]     * f.x;
            p1 += m[4 * c + 1] * f.y;
            p2 += m[4 * c + 2] * f.z;
            p3 += m[4 * c + 3] * f.w;
        }
        float pp = (p0 + p1) + (p2 + p3);
        pp += __shfl_xor_sync(0xffffffffu, pp, 1);
        if (h == 0) cbuf[part * 64 + row] = pp;
    }
    __syncthreads();

    // r = Wrp @ c + brp -> g_r
    {
        int o = tid >> 1, h2 = tid & 1;
        const float* wr = &Wrp[o * NH + h2 * 64];
        const float* cc = &cbuf[h2 * 64];
        float s = 0.f;
        #pragma unroll 8
        for (int mm = 0; mm < 64; mm++) s += __ldg(&wr[mm]) * cc[mm];
        s += __shfl_xor_sync(0xffffffffu, s, 1);
        if (h2 == 0) g_r[b * NH + o] = s + __ldg(&brp[o]);
    }
}

// ============================================================================
// K3: out[64 x 32000] = r @ Wout^T + bout.  250 CTAs, tile 64b x 128v.
// ============================================================================
#define K3_RST 65
#define K3_WST 129
#define K3_WS  (128 * K3_RST)
#define K3_SMEMF (K3_WS + 128 * K3_WST)

__global__ void __launch_bounds__(256, 2)
k3_kernel(const float* __restrict__ Wout, const float* __restrict__ bout,
          float* __restrict__ out)
{
    extern __shared__ float sm[];
    float* rs = sm;
    float* Ws = sm + K3_WS;
    const int tid = threadIdx.x;
    const int v0  = blockIdx.x * 128;
    const int ty  = tid >> 4, tx = tid & 15;

    for (int idx = tid; idx < 64 * 128; idx += 256) {
        int bb = idx >> 7, k = idx & 127;
        rs[k * K3_RST + bb] = g_r[idx];
    }
    for (int idx = tid; idx < 128 * 128; idx += 256) {
        int vv = idx >> 7, k = idx & 127;
        Ws[k * K3_WST + vv] = __ldg(&Wout[(size_t)(v0 + vv) * NH + k]);
    }
    __syncthreads();

    float acc0[4][4], acc1[4][4];
    #pragma unroll
    for (int i = 0; i < 4; i++)
        #pragma unroll
        for (int j = 0; j < 4; j++) { acc0[i][j] = 0.f; acc1[i][j] = 0.f; }

    #pragma unroll 4
    for (int k = 0; k < 128; k++) {
        float a[4], b0[4], b1[4];
        #pragma unroll
        for (int i = 0; i < 4; i++) a[i]  = rs[k * K3_RST + 4 * ty + i];
        #pragma unroll
        for (int j = 0; j < 4; j++) b0[j] = Ws[k * K3_WST + 16 * j + tx];
        #pragma unroll
        for (int j = 0; j < 4; j++) b1[j] = Ws[k * K3_WST + 64 + 16 * j + tx];
        #pragma unroll
        for (int i = 0; i < 4; i++)
            #pragma unroll
            for (int j = 0; j < 4; j++) {
                acc0[i][j] += a[i] * b0[j];
                acc1[i][j] += a[i] * b1[j];
            }
    }

    #pragma unroll
    for (int j = 0; j < 4; j++) {
        float bj0 = __ldg(&bout[v0 + 16 * j + tx]);
        float bj1 = __ldg(&bout[v0 + 64 + 16 * j + tx]);
        #pragma unroll
        for (int i = 0; i < 4; i++) {
            size_t base = (size_t)(4 * ty + i) * NV + v0;
            out[base + 16 * j + tx]      = acc0[i][j] + bj0;
            out[base + 64 + 16 * j + tx] = acc1[i][j] + bj1;
        }
    }
}

// ============================================================================
extern "C" void kernel_launch(void* const* d_in, const int* in_sizes, int n_in,
                              void* d_out, int out_size)
{
    const int*   seq   = (const int*)d_in[0];
    const float* embed = (const float*)d_in[1];
    const float* W1    = (const float*)d_in[2];
    const float* b1    = (const float*)d_in[3];
    const float* W2    = (const float*)d_in[4];
    const float* b2    = (const float*)d_in[5];
    const float* gamma = (const float*)d_in[6];
    const float* beta  = (const float*)d_in[7];
    const float* Wsem  = (const float*)d_in[8];
    const float* Wepi  = (const float*)d_in[9];
    const float* Wrp   = (const float*)d_in[10];
    const float* brp   = (const float*)d_in[11];
    const float* Wout  = (const float*)d_in[12];
    const float* bout  = (const float*)d_in[13];
    float* out = (float*)d_out;

    cudaFuncSetAttribute(k1_kernel, cudaFuncAttributeMaxDynamicSharedMemorySize,
                         K1_SMEMF * (int)sizeof(float));
    cudaFuncSetAttribute(k3_kernel, cudaFuncAttributeMaxDynamicSharedMemorySize,
                         K3_SMEMF * (int)sizeof(float));

    k1_kernel<<<NV / 64, 256, K1_SMEMF * sizeof(float)>>>(
        embed, W1, b1, W2, b2, gamma, beta, Wsem, Wepi);
    k2_kernel<<<NB, 256>>>(seq, Wrp, brp);
    k3_kernel<<<NV / 128, 256, K3_SMEMF * sizeof(float)>>>(Wout, bout, out);
}

// round 15
// speedup vs baseline: 1.5043x; 1.1500x over previous
#include <cuda_runtime.h>
#include <cuda_bf16.h>

#define NV 32000
#define NB 64
#define NL 1024
#define NH 128

// scratch (no allocs allowed)
__device__ float  g_tab[NV * NH];   // [v][128]: ks in 0..63, ke in 64..127
__device__ float2 g_nrm[NV];        // per-vocab (||ks||^2, ||ke||^2)
__device__ float  g_r[NB * NH];     // [b][128]

// ============================================================================
// K1: vocab table. (byte-identical to the measured 689.6us R12 round)
// ============================================================================
#define XST 68
#define W2ST 132
#define K1_XS   0
#define K1_T1   8704
#define K1_WB   13056
#define K1_RED  21760
#define K1_SMEMF 22272

__global__ void __launch_bounds__(256, 2)
k1_kernel(const float* __restrict__ embed,
          const float* __restrict__ W1, const float* __restrict__ b1,
          const float* __restrict__ W2, const float* __restrict__ b2,
          const float* __restrict__ gamma, const float* __restrict__ beta,
          const float* __restrict__ Wsem, const float* __restrict__ Wepi)
{
    extern __shared__ float sm[];
    float* Xs  = sm + K1_XS;
    float* T1p = sm + K1_T1;
    float* Wb  = sm + K1_WB;
    float* red = sm + K1_RED;

    const int tid = threadIdx.x;
    const int v0  = blockIdx.x * 64;
    const int ty  = tid >> 4, tx = tid & 15;

    for (int idx = tid; idx < 64 * 128; idx += 256) {
        int r = idx >> 7, h = idx & 127;
        Xs[h * XST + r] = __ldg(&embed[(size_t)(v0 + r) * NH + h]);
    }
    __syncthreads();

    float xacc[4][8];
    #pragma unroll
    for (int g = 0; g < 2; g++)
        #pragma unroll
        for (int j = 0; j < 4; j++) {
            int c = g * 64 + 4 * tx + j;
            float bj = __ldg(&b2[c]);
            float4 e = *(const float4*)&Xs[c * XST + 4 * ty];
            xacc[0][g * 4 + j] = e.x + bj;
            xacc[1][g * 4 + j] = e.y + bj;
            xacc[2][g * 4 + j] = e.z + bj;
            xacc[3][g * 4 + j] = e.w + bj;
        }

    for (int p = 0; p < 4; p++) {
        for (int idx = tid; idx < 64 * 128; idx += 256) {
            int k = idx & 127, c = idx >> 7;
            Wb[k * XST + c] = __ldg(&W1[(p * 64 + c) * NH + k]);
        }
        __syncthreads();

        float t1[4][4];
        #pragma unroll
        for (int i = 0; i < 4; i++)
            #pragma unroll
            for (int j = 0; j < 4; j++) t1[i][j] = 0.f;
        #pragma unroll 8
        for (int k = 0; k < 128; k++) {
            float4 av = *(const float4*)&Xs[k * XST + 4 * ty];
            float4 bv = *(const float4*)&Wb[k * XST + 4 * tx];
            float a[4] = {av.x, av.y, av.z, av.w};
            float b[4] = {bv.x, bv.y, bv.z, bv.w};
            #pragma unroll
            for (int i = 0; i < 4; i++)
                #pragma unroll
                for (int j = 0; j < 4; j++) t1[i][j] += a[i] * b[j];
        }
        #pragma unroll
        for (int j = 0; j < 4; j++) {
            int c = 4 * tx + j;
            float bj = __ldg(&b1[p * 64 + c]);
            float4 o;
            o.x = fmaxf(t1[0][j] + bj, 0.f);
            o.y = fmaxf(t1[1][j] + bj, 0.f);
            o.z = fmaxf(t1[2][j] + bj, 0.f);
            o.w = fmaxf(t1[3][j] + bj, 0.f);
            *(float4*)&T1p[c * XST + 4 * ty] = o;
        }
        __syncthreads();

        for (int idx = tid; idx < 64 * 128; idx += 256) {
            int kk = idx & 63, c = idx >> 6;
            Wb[kk * W2ST + c] = __ldg(&W2[c * 256 + p * 64 + kk]);
        }
        __syncthreads();

        #pragma unroll 8
        for (int kk = 0; kk < 64; kk++) {
            float4 av = *(const float4*)&T1p[kk * XST + 4 * ty];
            float4 b0 = *(const float4*)&Wb[kk * W2ST + 4 * tx];
            float4 b1v = *(const float4*)&Wb[kk * W2ST + 64 + 4 * tx];
            float a[4] = {av.x, av.y, av.z, av.w};
            float b[8] = {b0.x, b0.y, b0.z, b0.w, b1v.x, b1v.y, b1v.z, b1v.w};
            #pragma unroll
            for (int i = 0; i < 4; i++)
                #pragma unroll
                for (int j = 0; j < 8; j++) xacc[i][j] += a[i] * b[j];
        }
        __syncthreads();
    }

    #pragma unroll
    for (int g = 0; g < 2; g++)
        #pragma unroll
        for (int j = 0; j < 4; j++) {
            int c = g * 64 + 4 * tx + j;
            float4 o;
            o.x = xacc[0][g * 4 + j];
            o.y = xacc[1][g * 4 + j];
            o.z = xacc[2][g * 4 + j];
            o.w = xacc[3][g * 4 + j];
            *(float4*)&Xs[c * XST + 4 * ty] = o;
        }
    __syncthreads();

    {
        int r = tid & 63, qq = tid >> 6;
        float s1 = 0.f, s2 = 0.f;
        #pragma unroll 8
        for (int hh = 0; hh < 32; hh++) {
            float x = Xs[(qq * 32 + hh) * XST + r];
            s1 += x; s2 += x * x;
        }
        red[qq * 64 + r]       = s1;
        red[256 + qq * 64 + r] = s2;
        __syncthreads();
        float S1 = red[r] + red[64 + r] + red[128 + r] + red[192 + r];
        float S2 = red[256 + r] + red[320 + r] + red[384 + r] + red[448 + r];
        float mu   = S1 * (1.f / 128.f);
        float var  = S2 * (1.f / 128.f) - mu * mu;
        float rstd = rsqrtf(var + 1e-5f);
        #pragma unroll 8
        for (int hh = 0; hh < 32; hh++) {
            int h = qq * 32 + hh;
            float x = Xs[h * XST + r];
            Xs[h * XST + r] = (x - mu) * rstd * __ldg(&gamma[h]) + __ldg(&beta[h]);
        }
    }
    __syncthreads();

    for (int p = 0; p < 2; p++) {
        const float* Wk = p ? Wepi : Wsem;
        for (int idx = tid; idx < 64 * 128; idx += 256) {
            int k = idx & 127, c = idx >> 7;
            Wb[k * XST + c] = __ldg(&Wk[c * NH + k]);
        }
        __syncthreads();
        float acc[4][4];
        #pragma unroll
        for (int i = 0; i < 4; i++)
            #pragma unroll
            for (int j = 0; j < 4; j++) acc[i][j] = 0.f;
        #pragma unroll 8
        for (int k = 0; k < 128; k++) {
            float4 av = *(const float4*)&Xs[k * XST + 4 * ty];
            float4 bv = *(const float4*)&Wb[k * XST + 4 * tx];
            float a[4] = {av.x, av.y, av.z, av.w};
            float b[4] = {bv.x, bv.y, bv.z, bv.w};
            #pragma unroll
            for (int i = 0; i < 4; i++)
                #pragma unroll
                for (int j = 0; j < 4; j++) acc[i][j] += a[i] * b[j];
        }
        #pragma unroll
        for (int i = 0; i < 4; i++) {
            float4 o;
            o.x = acc[i][0]; o.y = acc[i][1]; o.z = acc[i][2]; o.w = acc[i][3];
            *(float4*)&g_tab[(size_t)(v0 + 4 * ty + i) * NH + p * 64 + 4 * tx] = o;
        }
        #pragma unroll
        for (int i = 0; i < 4; i++) {
            float s = acc[i][0] * acc[i][0] + acc[i][1] * acc[i][1]
                    + acc[i][2] * acc[i][2] + acc[i][3] * acc[i][3];
            s += __shfl_xor_sync(0xffffffffu, s, 1);
            s += __shfl_xor_sync(0xffffffffu, s, 2);
            s += __shfl_xor_sync(0xffffffffu, s, 4);
            s += __shfl_xor_sync(0xffffffffu, s, 8);
            if (tx == 0) {
                float* gn = (float*)&g_nrm[v0 + 4 * ty + i];
                gn[p] = s;
            }
        }
        __syncthreads();
    }
}

// ============================================================================
// K2: frozen R12 loop skeleton. ONE producer swap: per-step norms/inv come
// from smem tables precomputed once before the loop (bit-identical formula),
// replacing the per-step LDG + sqrt/fmax/rcp chain with two broadcast LDS.
// ============================================================================
__global__ void __launch_bounds__(256, 1)
k2_kernel(const int* __restrict__ seq,
          const float* __restrict__ Wrp, const float* __restrict__ brp)
{
    __shared__ int    seqs[NL];
    __shared__ float  slot[2][128];
    __shared__ float  wred[2][8];
    __shared__ float  cbuf[128];
    __shared__ float2 nrm2[NL];     // (||ks||^2, ||ke||^2) per position
    __shared__ float2 inv2[NL];     // (1/max(sqrt(.x),eps), 1/max(sqrt(.y),eps))

    const int tid  = threadIdx.x;
    const int b    = blockIdx.x;
    const int part = tid >> 7;          // 0 = s, 1 = e
    const int pt   = tid & 127;
    const int row  = pt >> 1;
    const int h    = pt & 1;
    const int lane = tid & 31;
    const int warp = tid >> 5;

    for (int idx = tid; idx < NL; idx += 256) seqs[idx] = seq[b * NL + idx];
    __syncthreads();

    // precompute per-position norms + inverse norms (same formula as before)
    for (int idx = tid; idx < NL; idx += 256) {
        float2 nr = __ldg(&g_nrm[seqs[idx]]);
        nrm2[idx] = nr;
        float2 iv;
        iv.x = 1.f / fmaxf(sqrtf(nr.x), 1e-12f);
        iv.y = 1.f / fmaxf(sqrtf(nr.y), 1e-12f);
        inv2[idx] = iv;
    }

    // preload k_0
    if (tid < 128) slot[0][tid] = __ldg(&g_tab[(size_t)seqs[0] * NH + tid]);
    __syncthreads();

    float2 cn  = nrm2[0];
    float2 ci2 = inv2[0];
    float cinv = part ? ci2.y : ci2.x;

    float m[32];
    #pragma unroll
    for (int c = 0; c < 32; c++) m[c] = 0.f;

    const int kbase = part * 64 + h * 32;

    for (int t = 0; t < NL - 1; t++) {
        const int par = t & 1;
        const int nt  = t + 1;

        // prefetch k_{t+1}; norms/inv for t+1 from the smem tables
        float pv = 0.f;
        if (tid < 128) pv = __ldg(&g_tab[(size_t)seqs[nt] * NH + tid]);
        float2 pn  = nrm2[nt];
        float2 pi2 = inv2[nt];
        float  pinv = part ? pi2.y : pi2.x;

        // load my 32 k values
        float kv[32];
        const float* kb = &slot[par][kbase];
        #pragma unroll
        for (int c = 0; c < 8; c++) {
            float4 f = *(const float4*)&kb[4 * c];
            kv[4 * c] = f.x; kv[4 * c + 1] = f.y;
            kv[4 * c + 2] = f.z; kv[4 * c + 3] = f.w;
        }

        // matvec partial (4-way split accumulation)
        float p0 = 0.f, p1 = 0.f, p2 = 0.f, p3 = 0.f;
        #pragma unroll
        for (int c = 0; c < 8; c++) {
            p0 += m[4 * c]     * kv[4 * c];
            p1 += m[4 * c + 1] * kv[4 * c + 1];
            p2 += m[4 * c + 2] * kv[4 * c + 2];
            p3 += m[4 * c + 3] * kv[4 * c + 3];
        }
        float pp = (p0 + p1) + (p2 + p3);
        pp += __shfl_xor_sync(0xffffffffu, pp, 1);      // combine halves

        float kelem = slot[par][part * 64 + row];
        float dd = kelem - pp * cinv;

        // err^2 reduce: contributing lanes are h==0 (even lanes), 4 levels
        float v = (h == 0) ? dd * dd : 0.f;
        v += __shfl_xor_sync(0xffffffffu, v, 2);
        v += __shfl_xor_sync(0xffffffffu, v, 4);
        v += __shfl_xor_sync(0xffffffffu, v, 8);
        v += __shfl_xor_sync(0xffffffffu, v, 16);
        if (lane == 0) wred[par][warp] = v;

        // commit prefetched k_{t+1} (opposite parity buffer)
        if (tid < 128) slot[nt & 1][tid] = pv;

        __syncthreads();    // the only barrier in the step

        float4 w0 = *(const float4*)&wred[par][0];
        float4 w1 = *(const float4*)&wred[par][4];
        float es2 = (w0.x + w0.y) + (w0.z + w0.w);
        float ee2 = (w1.x + w1.y) + (w1.z + w1.w);
        bool fire = (es2 >= (0.7f * 0.7f) * cn.x) ||
                    (ee2 >= (0.7f * 0.7f) * cn.y);
        float wf   = part ? ((float)nt * (1.f / (float)NL)) : 1.f;
        float coef = (fire ? 0.05f : 0.f) * wf * cinv * dd;
        #pragma unroll
        for (int c = 0; c < 32; c++) m[c] += coef * kv[c];

        // roll prefetched norms into current
        cn = pn; cinv = pinv;
    }

    // final: q = tab row of seq[b][L-1], sits in slot[1]. c = M @ q-part (raw).
    {
        const float* kb = &slot[1][kbase];
        float p0 = 0.f, p1 = 0.f, p2 = 0.f, p3 = 0.f;
        #pragma unroll
        for (int c = 0; c < 8; c++) {
            float4 f = *(const float4*)&kb[4 * c];
            p0 += m[4 * c]     * f.x;
            p1 += m[4 * c + 1] * f.y;
            p2 += m[4 * c + 2] * f.z;
            p3 += m[4 * c + 3] * f.w;
        }
        float pp = (p0 + p1) + (p2 + p3);
        pp += __shfl_xor_sync(0xffffffffu, pp, 1);
        if (h == 0) cbuf[part * 64 + row] = pp;
    }
    __syncthreads();

    // r = Wrp @ c + brp -> g_r
    {
        int o = tid >> 1, h2 = tid & 1;
        const float* wr = &Wrp[o * NH + h2 * 64];
        const float* cc = &cbuf[h2 * 64];
        float s = 0.f;
        #pragma unroll 8
        for (int mm = 0; mm < 64; mm++) s += __ldg(&wr[mm]) * cc[mm];
        s += __shfl_xor_sync(0xffffffffu, s, 1);
        if (h2 == 0) g_r[b * NH + o] = s + __ldg(&brp[o]);
    }
}

// ============================================================================
// K3: out[64 x 32000] = r @ Wout^T + bout.  250 CTAs, tile 64b x 128v.
// ============================================================================
#define K3_RST 65
#define K3_WST 129
#define K3_WS  (128 * K3_RST)
#define K3_SMEMF (K3_WS + 128 * K3_WST)

__global__ void __launch_bounds__(256, 2)
k3_kernel(const float* __restrict__ Wout, const float* __restrict__ bout,
          float* __restrict__ out)
{
    extern __shared__ float sm[];
    float* rs = sm;
    float* Ws = sm + K3_WS;
    const int tid = threadIdx.x;
    const int v0  = blockIdx.x * 128;
    const int ty  = tid >> 4, tx = tid & 15;

    for (int idx = tid; idx < 64 * 128; idx += 256) {
        int bb = idx >> 7, k = idx & 127;
        rs[k * K3_RST + bb] = g_r[idx];
    }
    for (int idx = tid; idx < 128 * 128; idx += 256) {
        int vv = idx >> 7, k = idx & 127;
        Ws[k * K3_WST + vv] = __ldg(&Wout[(size_t)(v0 + vv) * NH + k]);
    }
    __syncthreads();

    float acc0[4][4], acc1[4][4];
    #pragma unroll
    for (int i = 0; i < 4; i++)
        #pragma unroll
        for (int j = 0; j < 4; j++) { acc0[i][j] = 0.f; acc1[i][j] = 0.f; }

    #pragma unroll 4
    for (int k = 0; k < 128; k++) {
        float a[4], b0[4], b1[4];
        #pragma unroll
        for (int i = 0; i < 4; i++) a[i]  = rs[k * K3_RST + 4 * ty + i];
        #pragma unroll
        for (int j = 0; j < 4; j++) b0[j] = Ws[k * K3_WST + 16 * j + tx];
        #pragma unroll
        for (int j = 0; j < 4; j++) b1[j] = Ws[k * K3_WST + 64 + 16 * j + tx];
        #pragma unroll
        for (int i = 0; i < 4; i++)
            #pragma unroll
            for (int j = 0; j < 4; j++) {
                acc0[i][j] += a[i] * b0[j];
                acc1[i][j] += a[i] * b1[j];
            }
    }

    #pragma unroll
    for (int j = 0; j < 4; j++) {
        float bj0 = __ldg(&bout[v0 + 16 * j + tx]);
        float bj1 = __ldg(&bout[v0 + 64 + 16 * j + tx]);
        #pragma unroll
        for (int i = 0; i < 4; i++) {
            size_t base = (size_t)(4 * ty + i) * NV + v0;
            out[base + 16 * j + tx]      = acc0[i][j] + bj0;
            out[base + 64 + 16 * j + tx] = acc1[i][j] + bj1;
        }
    }
}

// ============================================================================
extern "C" void kernel_launch(void* const* d_in, const int* in_sizes, int n_in,
                              void* d_out, int out_size)
{
    const int*   seq   = (const int*)d_in[0];
    const float* embed = (const float*)d_in[1];
    const float* W1    = (const float*)d_in[2];
    const float* b1    = (const float*)d_in[3];
    const float* W2    = (const float*)d_in[4];
    const float* b2    = (const float*)d_in[5];
    const float* gamma = (const float*)d_in[6];
    const float* beta  = (const float*)d_in[7];
    const float* Wsem  = (const float*)d_in[8];
    const float* Wepi  = (const float*)d_in[9];
    const float* Wrp   = (const float*)d_in[10];
    const float* brp   = (const float*)d_in[11];
    const float* Wout  = (const float*)d_in[12];
    const float* bout  = (const float*)d_in[13];
    float* out = (float*)d_out;

    cudaFuncSetAttribute(k1_kernel, cudaFuncAttributeMaxDynamicSharedMemorySize,
                         K1_SMEMF * (int)sizeof(float));
    cudaFuncSetAttribute(k3_kernel, cudaFuncAttributeMaxDynamicSharedMemorySize,
                         K3_SMEMF * (int)sizeof(float));

    k1_kernel<<<NV / 64, 256, K1_SMEMF * sizeof(float)>>>(
        embed, W1, b1, W2, b2, gamma, beta, Wsem, Wepi);
    k2_kernel<<<NB, 256>>>(seq, Wrp, brp);
    k3_kernel<<<NV / 128, 256, K3_SMEMF * sizeof(float)>>>(Wout, bout, out);
}

// round 16
// speedup vs baseline: 1.5424x; 1.0254x over previous
#include <cuda_runtime.h>
#include <cuda_bf16.h>

#define NV 32000
#define NB 64
#define NL 1024
#define NH 128

// scratch (no allocs allowed)
__device__ float  g_tab[NV * NH];   // [v][128]: ks in 0..63, ke in 64..127
__device__ float2 g_nrm[NV];        // per-vocab (||ks||^2, ||ke||^2)
__device__ float  g_r[NB * NH];     // [b][128]

// ============================================================================
// K1: vocab table. (byte-identical to the measured 614.4us round)
// ============================================================================
#define XST 68
#define W2ST 132
#define K1_XS   0
#define K1_T1   8704
#define K1_WB   13056
#define K1_RED  21760
#define K1_SMEMF 22272

__global__ void __launch_bounds__(256, 2)
k1_kernel(const float* __restrict__ embed,
          const float* __restrict__ W1, const float* __restrict__ b1,
          const float* __restrict__ W2, const float* __restrict__ b2,
          const float* __restrict__ gamma, const float* __restrict__ beta,
          const float* __restrict__ Wsem, const float* __restrict__ Wepi)
{
    extern __shared__ float sm[];
    float* Xs  = sm + K1_XS;
    float* T1p = sm + K1_T1;
    float* Wb  = sm + K1_WB;
    float* red = sm + K1_RED;

    const int tid = threadIdx.x;
    const int v0  = blockIdx.x * 64;
    const int ty  = tid >> 4, tx = tid & 15;

    for (int idx = tid; idx < 64 * 128; idx += 256) {
        int r = idx >> 7, h = idx & 127;
        Xs[h * XST + r] = __ldg(&embed[(size_t)(v0 + r) * NH + h]);
    }
    __syncthreads();

    float xacc[4][8];
    #pragma unroll
    for (int g = 0; g < 2; g++)
        #pragma unroll
        for (int j = 0; j < 4; j++) {
            int c = g * 64 + 4 * tx + j;
            float bj = __ldg(&b2[c]);
            float4 e = *(const float4*)&Xs[c * XST + 4 * ty];
            xacc[0][g * 4 + j] = e.x + bj;
            xacc[1][g * 4 + j] = e.y + bj;
            xacc[2][g * 4 + j] = e.z + bj;
            xacc[3][g * 4 + j] = e.w + bj;
        }

    for (int p = 0; p < 4; p++) {
        for (int idx = tid; idx < 64 * 128; idx += 256) {
            int k = idx & 127, c = idx >> 7;
            Wb[k * XST + c] = __ldg(&W1[(p * 64 + c) * NH + k]);
        }
        __syncthreads();

        float t1[4][4];
        #pragma unroll
        for (int i = 0; i < 4; i++)
            #pragma unroll
            for (int j = 0; j < 4; j++) t1[i][j] = 0.f;
        #pragma unroll 8
        for (int k = 0; k < 128; k++) {
            float4 av = *(const float4*)&Xs[k * XST + 4 * ty];
            float4 bv = *(const float4*)&Wb[k * XST + 4 * tx];
            float a[4] = {av.x, av.y, av.z, av.w};
            float b[4] = {bv.x, bv.y, bv.z, bv.w};
            #pragma unroll
            for (int i = 0; i < 4; i++)
                #pragma unroll
                for (int j = 0; j < 4; j++) t1[i][j] += a[i] * b[j];
        }
        #pragma unroll
        for (int j = 0; j < 4; j++) {
            int c = 4 * tx + j;
            float bj = __ldg(&b1[p * 64 + c]);
            float4 o;
            o.x = fmaxf(t1[0][j] + bj, 0.f);
            o.y = fmaxf(t1[1][j] + bj, 0.f);
            o.z = fmaxf(t1[2][j] + bj, 0.f);
            o.w = fmaxf(t1[3][j] + bj, 0.f);
            *(float4*)&T1p[c * XST + 4 * ty] = o;
        }
        __syncthreads();

        for (int idx = tid; idx < 64 * 128; idx += 256) {
            int kk = idx & 63, c = idx >> 6;
            Wb[kk * W2ST + c] = __ldg(&W2[c * 256 + p * 64 + kk]);
        }
        __syncthreads();

        #pragma unroll 8
        for (int kk = 0; kk < 64; kk++) {
            float4 av = *(const float4*)&T1p[kk * XST + 4 * ty];
            float4 b0 = *(const float4*)&Wb[kk * W2ST + 4 * tx];
            float4 b1v = *(const float4*)&Wb[kk * W2ST + 64 + 4 * tx];
            float a[4] = {av.x, av.y, av.z, av.w};
            float b[8] = {b0.x, b0.y, b0.z, b0.w, b1v.x, b1v.y, b1v.z, b1v.w};
            #pragma unroll
            for (int i = 0; i < 4; i++)
                #pragma unroll
                for (int j = 0; j < 8; j++) xacc[i][j] += a[i] * b[j];
        }
        __syncthreads();
    }

    #pragma unroll
    for (int g = 0; g < 2; g++)
        #pragma unroll
        for (int j = 0; j < 4; j++) {
            int c = g * 64 + 4 * tx + j;
            float4 o;
            o.x = xacc[0][g * 4 + j];
            o.y = xacc[1][g * 4 + j];
            o.z = xacc[2][g * 4 + j];
            o.w = xacc[3][g * 4 + j];
            *(float4*)&Xs[c * XST + 4 * ty] = o;
        }
    __syncthreads();

    {
        int r = tid & 63, qq = tid >> 6;
        float s1 = 0.f, s2 = 0.f;
        #pragma unroll 8
        for (int hh = 0; hh < 32; hh++) {
            float x = Xs[(qq * 32 + hh) * XST + r];
            s1 += x; s2 += x * x;
        }
        red[qq * 64 + r]       = s1;
        red[256 + qq * 64 + r] = s2;
        __syncthreads();
        float S1 = red[r] + red[64 + r] + red[128 + r] + red[192 + r];
        float S2 = red[256 + r] + red[320 + r] + red[384 + r] + red[448 + r];
        float mu   = S1 * (1.f / 128.f);
        float var  = S2 * (1.f / 128.f) - mu * mu;
        float rstd = rsqrtf(var + 1e-5f);
        #pragma unroll 8
        for (int hh = 0; hh < 32; hh++) {
            int h = qq * 32 + hh;
            float x = Xs[h * XST + r];
            Xs[h * XST + r] = (x - mu) * rstd * __ldg(&gamma[h]) + __ldg(&beta[h]);
        }
    }
    __syncthreads();

    for (int p = 0; p < 2; p++) {
        const float* Wk = p ? Wepi : Wsem;
        for (int idx = tid; idx < 64 * 128; idx += 256) {
            int k = idx & 127, c = idx >> 7;
            Wb[k * XST + c] = __ldg(&Wk[c * NH + k]);
        }
        __syncthreads();
        float acc[4][4];
        #pragma unroll
        for (int i = 0; i < 4; i++)
            #pragma unroll
            for (int j = 0; j < 4; j++) acc[i][j] = 0.f;
        #pragma unroll 8
        for (int k = 0; k < 128; k++) {
            float4 av = *(const float4*)&Xs[k * XST + 4 * ty];
            float4 bv = *(const float4*)&Wb[k * XST + 4 * tx];
            float a[4] = {av.x, av.y, av.z, av.w};
            float b[4] = {bv.x, bv.y, bv.z, bv.w};
            #pragma unroll
            for (int i = 0; i < 4; i++)
                #pragma unroll
                for (int j = 0; j < 4; j++) acc[i][j] += a[i] * b[j];
        }
        #pragma unroll
        for (int i = 0; i < 4; i++) {
            float4 o;
            o.x = acc[i][0]; o.y = acc[i][1]; o.z = acc[i][2]; o.w = acc[i][3];
            *(float4*)&g_tab[(size_t)(v0 + 4 * ty + i) * NH + p * 64 + 4 * tx] = o;
        }
        #pragma unroll
        for (int i = 0; i < 4; i++) {
            float s = acc[i][0] * acc[i][0] + acc[i][1] * acc[i][1]
                    + acc[i][2] * acc[i][2] + acc[i][3] * acc[i][3];
            s += __shfl_xor_sync(0xffffffffu, s, 1);
            s += __shfl_xor_sync(0xffffffffu, s, 2);
            s += __shfl_xor_sync(0xffffffffu, s, 4);
            s += __shfl_xor_sync(0xffffffffu, s, 8);
            if (tx == 0) {
                float* gn = (float*)&g_nrm[v0 + 4 * ty + i];
                gn[p] = s;
            }
        }
        __syncthreads();
    }
}

// ============================================================================
// K2: R15 winning kernel with ONE change — loop rotation of the g_tab
// prefetch. The LDG for k_{t+2} is issued in the post-barrier gate/update
// section of step t (not at step t+1's top), so by the time it is committed
// (mid-step t+1, pre-barrier) it has had ~a full step of latency slack and
// never stalls the commit/barrier. 2-slot parity buffer, norm/inv smem
// tables, shfl chains, thread map: all byte-identical to R15.
// ============================================================================
__global__ void __launch_bounds__(256, 1)
k2_kernel(const int* __restrict__ seq,
          const float* __restrict__ Wrp, const float* __restrict__ brp)
{
    __shared__ int    seqs[NL];
    __shared__ float  slot[2][128];
    __shared__ float  wred[2][8];
    __shared__ float  cbuf[128];
    __shared__ float2 nrm2[NL];     // (||ks||^2, ||ke||^2) per position
    __shared__ float2 inv2[NL];     // 1/max(sqrt(.),eps)

    const int tid  = threadIdx.x;
    const int b    = blockIdx.x;
    const int part = tid >> 7;          // 0 = s, 1 = e
    const int pt   = tid & 127;
    const int row  = pt >> 1;
    const int h    = pt & 1;
    const int lane = tid & 31;
    const int warp = tid >> 5;

    for (int idx = tid; idx < NL; idx += 256) seqs[idx] = seq[b * NL + idx];
    __syncthreads();

    // precompute per-position norms + inverse norms (same formula)
    for (int idx = tid; idx < NL; idx += 256) {
        float2 nr = __ldg(&g_nrm[seqs[idx]]);
        nrm2[idx] = nr;
        float2 iv;
        iv.x = 1.f / fmaxf(sqrtf(nr.x), 1e-12f);
        iv.y = 1.f / fmaxf(sqrtf(nr.y), 1e-12f);
        inv2[idx] = iv;
    }

    // preload k_0 into slot 0; pv holds k_1 (committed at t=0)
    float pv = 0.f;
    if (tid < 128) {
        slot[0][tid] = __ldg(&g_tab[(size_t)seqs[0] * NH + tid]);
        pv           = __ldg(&g_tab[(size_t)seqs[1] * NH + tid]);
    }
    __syncthreads();

    float2 cn  = nrm2[0];
    float2 ci2 = inv2[0];
    float cinv = part ? ci2.y : ci2.x;

    float m[32];
    #pragma unroll
    for (int c = 0; c < 32; c++) m[c] = 0.f;

    const int kbase = part * 64 + h * 32;

    for (int t = 0; t < NL - 1; t++) {
        const int par = t & 1;
        const int nt  = t + 1;

        // norms/inv for t+1 from the smem tables (off critical path)
        float2 pn  = nrm2[nt];
        float2 pi2 = inv2[nt];
        float  pinv = part ? pi2.y : pi2.x;

        // load my 32 k values
        float kv[32];
        const float* kb = &slot[par][kbase];
        #pragma unroll
        for (int c = 0; c < 8; c++) {
            float4 f = *(const float4*)&kb[4 * c];
            kv[4 * c] = f.x; kv[4 * c + 1] = f.y;
            kv[4 * c + 2] = f.z; kv[4 * c + 3] = f.w;
        }

        // matvec partial (4-way split accumulation)
        float p0 = 0.f, p1 = 0.f, p2 = 0.f, p3 = 0.f;
        #pragma unroll
        for (int c = 0; c < 8; c++) {
            p0 += m[4 * c]     * kv[4 * c];
            p1 += m[4 * c + 1] * kv[4 * c + 1];
            p2 += m[4 * c + 2] * kv[4 * c + 2];
            p3 += m[4 * c + 3] * kv[4 * c + 3];
        }
        float pp = (p0 + p1) + (p2 + p3);
        pp += __shfl_xor_sync(0xffffffffu, pp, 1);      // combine halves

        float kelem = slot[par][part * 64 + row];
        float dd = kelem - pp * cinv;

        // err^2 reduce: contributing lanes are h==0 (even lanes), 4 levels
        float v = (h == 0) ? dd * dd : 0.f;
        v += __shfl_xor_sync(0xffffffffu, v, 2);
        v += __shfl_xor_sync(0xffffffffu, v, 4);
        v += __shfl_xor_sync(0xffffffffu, v, 8);
        v += __shfl_xor_sync(0xffffffffu, v, 16);
        if (lane == 0) wred[par][warp] = v;

        // commit k_{t+1} (loaded a full step ago) to the opposite parity slot
        if (tid < 128) slot[nt & 1][tid] = pv;

        __syncthreads();    // the only barrier in the step

        float4 w0 = *(const float4*)&wred[par][0];
        float4 w1 = *(const float4*)&wred[par][4];
        float es2 = (w0.x + w0.y) + (w0.z + w0.w);
        float ee2 = (w1.x + w1.y) + (w1.z + w1.w);
        bool fire = (es2 >= (0.7f * 0.7f) * cn.x) ||
                    (ee2 >= (0.7f * 0.7f) * cn.y);
        float wf   = part ? ((float)nt * (1.f / (float)NL)) : 1.f;
        float coef = (fire ? 0.05f : 0.f) * wf * cinv * dd;
        #pragma unroll
        for (int c = 0; c < 32; c++) m[c] += coef * kv[c];

        // rotated prefetch: issue LDG for k_{t+2} here (post-barrier),
        // giving it a full step of slack before its commit next iteration
        if (tid < 128 && t + 2 < NL)
            pv = __ldg(&g_tab[(size_t)seqs[t + 2] * NH + tid]);

        // roll prefetched norms into current
        cn = pn; cinv = pinv;
    }

    // final: q = tab row of seq[b][L-1], sits in slot[1]. c = M @ q-part (raw).
    {
        const float* kb = &slot[1][kbase];
        float p0 = 0.f, p1 = 0.f, p2 = 0.f, p3 = 0.f;
        #pragma unroll
        for (int c = 0; c < 8; c++) {
            float4 f = *(const float4*)&kb[4 * c];
            p0 += m[4 * c]     * f.x;
            p1 += m[4 * c + 1] * f.y;
            p2 += m[4 * c + 2] * f.z;
            p3 += m[4 * c + 3] * f.w;
        }
        float pp = (p0 + p1) + (p2 + p3);
        pp += __shfl_xor_sync(0xffffffffu, pp, 1);
        if (h == 0) cbuf[part * 64 + row] = pp;
    }
    __syncthreads();

    // r = Wrp @ c + brp -> g_r
    {
        int o = tid >> 1, h2 = tid & 1;
        const float* wr = &Wrp[o * NH + h2 * 64];
        const float* cc = &cbuf[h2 * 64];
        float s = 0.f;
        #pragma unroll 8
        for (int mm = 0; mm < 64; mm++) s += __ldg(&wr[mm]) * cc[mm];
        s += __shfl_xor_sync(0xffffffffu, s, 1);
        if (h2 == 0) g_r[b * NH + o] = s + __ldg(&brp[o]);
    }
}

// ============================================================================
// K3: out[64 x 32000] = r @ Wout^T + bout.  250 CTAs, tile 64b x 128v.
// ============================================================================
#define K3_RST 65
#define K3_WST 129
#define K3_WS  (128 * K3_RST)
#define K3_SMEMF (K3_WS + 128 * K3_WST)

__global__ void __launch_bounds__(256, 2)
k3_kernel(const float* __restrict__ Wout, const float* __restrict__ bout,
          float* __restrict__ out)
{
    extern __shared__ float sm[];
    float* rs = sm;
    float* Ws = sm + K3_WS;
    const int tid = threadIdx.x;
    const int v0  = blockIdx.x * 128;
    const int ty  = tid >> 4, tx = tid & 15;

    for (int idx = tid; idx < 64 * 128; idx += 256) {
        int bb = idx >> 7, k = idx & 127;
        rs[k * K3_RST + bb] = g_r[idx];
    }
    for (int idx = tid; idx < 128 * 128; idx += 256) {
        int vv = idx >> 7, k = idx & 127;
        Ws[k * K3_WST + vv] = __ldg(&Wout[(size_t)(v0 + vv) * NH + k]);
    }
    __syncthreads();

    float acc0[4][4], acc1[4][4];
    #pragma unroll
    for (int i = 0; i < 4; i++)
        #pragma unroll
        for (int j = 0; j < 4; j++) { acc0[i][j] = 0.f; acc1[i][j] = 0.f; }

    #pragma unroll 4
    for (int k = 0; k < 128; k++) {
        float a[4], b0[4], b1[4];
        #pragma unroll
        for (int i = 0; i < 4; i++) a[i]  = rs[k * K3_RST + 4 * ty + i];
        #pragma unroll
        for (int j = 0; j < 4; j++) b0[j] = Ws[k * K3_WST + 16 * j + tx];
        #pragma unroll
        for (int j = 0; j < 4; j++) b1[j] = Ws[k * K3_WST + 64 + 16 * j + tx];
        #pragma unroll
        for (int i = 0; i < 4; i++)
            #pragma unroll
            for (int j = 0; j < 4; j++) {
                acc0[i][j] += a[i] * b0[j];
                acc1[i][j] += a[i] * b1[j];
            }
    }

    #pragma unroll
    for (int j = 0; j < 4; j++) {
        float bj0 = __ldg(&bout[v0 + 16 * j + tx]);
        float bj1 = __ldg(&bout[v0 + 64 + 16 * j + tx]);
        #pragma unroll
        for (int i = 0; i < 4; i++) {
            size_t base = (size_t)(4 * ty + i) * NV + v0;
            out[base + 16 * j + tx]      = acc0[i][j] + bj0;
            out[base + 64 + 16 * j + tx] = acc1[i][j] + bj1;
        }
    }
}

// ============================================================================
extern "C" void kernel_launch(void* const* d_in, const int* in_sizes, int n_in,
                              void* d_out, int out_size)
{
    const int*   seq   = (const int*)d_in[0];
    const float* embed = (const float*)d_in[1];
    const float* W1    = (const float*)d_in[2];
    const float* b1    = (const float*)d_in[3];
    const float* W2    = (const float*)d_in[4];
    const float* b2    = (const float*)d_in[5];
    const float* gamma = (const float*)d_in[6];
    const float* beta  = (const float*)d_in[7];
    const float* Wsem  = (const float*)d_in[8];
    const float* Wepi  = (const float*)d_in[9];
    const float* Wrp   = (const float*)d_in[10];
    const float* brp   = (const float*)d_in[11];
    const float* Wout  = (const float*)d_in[12];
    const float* bout  = (const float*)d_in[13];
    float* out = (float*)d_out;

    cudaFuncSetAttribute(k1_kernel, cudaFuncAttributeMaxDynamicSharedMemorySize,
                         K1_SMEMF * (int)sizeof(float));
    cudaFuncSetAttribute(k3_kernel, cudaFuncAttributeMaxDynamicSharedMemorySize,
                         K3_SMEMF * (int)sizeof(float));

    k1_kernel<<<NV / 64, 256, K1_SMEMF * sizeof(float)>>>(
        embed, W1, b1, W2, b2, gamma, beta, Wsem, Wepi);
    k2_kernel<<<NB, 256>>>(seq, Wrp, brp);
    k3_kernel<<<NV / 128, 256, K3_SMEMF * sizeof(float)>>>(Wout, bout, out);
}